// round 2
// baseline (speedup 1.0000x reference)
#include <cuda_runtime.h>
#include <cuda_bf16.h>
#include <cstdint>

// DynamicFeedForward:
//   input_value [4,2048,512] f32
//   mask_tensor [4,2048,32] i32 (JAX x64 disabled -> int32)
//   weight      [50000,512] f32
//   bias        [50000]     f32
// out[b,s,m] = relu( dot(input[b,s,:], weight[mask[b,s,m],:]) + bias[mask[b,s,m]] )

static constexpr int HIDDEN = 512;
static constexpr int NCAND  = 32;
static constexpr int THREADS = 256;   // 8 warps, 4 candidates per warp

__global__ __launch_bounds__(THREADS)
void dff_kernel(const float* __restrict__ inp,
                const int* __restrict__ mask,
                const float* __restrict__ W,
                const float* __restrict__ B,
                float* __restrict__ out,
                int n_tokens)
{
    int token = blockIdx.x;
    if (token >= n_tokens) return;

    const int wid  = threadIdx.x >> 5;
    const int lane = threadIdx.x & 31;

    // Stage this lane's slice of the input row into registers.
    // Lane l covers elements [l*4, l*4+4) at base offsets 0,128,256,384.
    const float* in_row = inp + (size_t)token * HIDDEN;
    const float4 a0 = *reinterpret_cast<const float4*>(in_row + 0   + lane * 4);
    const float4 a1 = *reinterpret_cast<const float4*>(in_row + 128 + lane * 4);
    const float4 a2 = *reinterpret_cast<const float4*>(in_row + 256 + lane * 4);
    const float4 a3 = *reinterpret_cast<const float4*>(in_row + 384 + lane * 4);

    const int* m = mask + (size_t)token * NCAND;
    float* o = out + (size_t)token * NCAND;

    #pragma unroll
    for (int c = 0; c < 4; c++) {
        const int cand = wid + c * 8;
        const int idx = __ldg(m + cand);
        const float* w = W + (size_t)idx * HIDDEN;

        const float4 b0 = *reinterpret_cast<const float4*>(w + 0   + lane * 4);
        const float4 b1 = *reinterpret_cast<const float4*>(w + 128 + lane * 4);
        const float4 b2 = *reinterpret_cast<const float4*>(w + 256 + lane * 4);
        const float4 b3 = *reinterpret_cast<const float4*>(w + 384 + lane * 4);

        float s = 0.f;
        s = fmaf(a0.x, b0.x, s); s = fmaf(a0.y, b0.y, s);
        s = fmaf(a0.z, b0.z, s); s = fmaf(a0.w, b0.w, s);
        s = fmaf(a1.x, b1.x, s); s = fmaf(a1.y, b1.y, s);
        s = fmaf(a1.z, b1.z, s); s = fmaf(a1.w, b1.w, s);
        s = fmaf(a2.x, b2.x, s); s = fmaf(a2.y, b2.y, s);
        s = fmaf(a2.z, b2.z, s); s = fmaf(a2.w, b2.w, s);
        s = fmaf(a3.x, b3.x, s); s = fmaf(a3.y, b3.y, s);
        s = fmaf(a3.z, b3.z, s); s = fmaf(a3.w, b3.w, s);

        // warp reduce
        #pragma unroll
        for (int off = 16; off > 0; off >>= 1)
            s += __shfl_xor_sync(0xFFFFFFFFu, s, off);

        if (lane == 0)
            o[cand] = fmaxf(s + __ldg(B + idx), 0.0f);
    }
}

extern "C" void kernel_launch(void* const* d_in, const int* in_sizes, int n_in,
                              void* d_out, int out_size)
{
    const float* inp  = (const float*)d_in[0];
    const int*   mask = (const int*)d_in[1];
    const float* W    = (const float*)d_in[2];
    const float* B    = (const float*)d_in[3];
    float* out = (float*)d_out;

    const int n_tokens = in_sizes[0] / HIDDEN;   // 8192

    dff_kernel<<<n_tokens, THREADS>>>(inp, mask, W, B, out, n_tokens);
}

// round 3
// speedup vs baseline: 1.3179x; 1.3179x over previous
#include <cuda_runtime.h>
#include <cuda_bf16.h>
#include <cstdint>

// DynamicFeedForward:
//   input_value [4,2048,512] f32
//   mask_tensor [4,2048,32] i32
//   weight      [50000,512] f32
//   bias        [50000]     f32
// out[b,s,m] = relu( dot(input[b,s,:], weight[mask[b,s,m],:]) + bias[mask[b,s,m]] )

static constexpr int HIDDEN  = 512;
static constexpr int NCAND   = 32;
static constexpr int THREADS = 256;   // 8 warps = 8 tokens per CTA

__device__ __forceinline__ float dot16(const float4 a0, const float4 a1,
                                       const float4 a2, const float4 a3,
                                       const float4 b0, const float4 b1,
                                       const float4 b2, const float4 b3)
{
    float s = 0.f;
    s = fmaf(a0.x, b0.x, s); s = fmaf(a0.y, b0.y, s);
    s = fmaf(a0.z, b0.z, s); s = fmaf(a0.w, b0.w, s);
    s = fmaf(a1.x, b1.x, s); s = fmaf(a1.y, b1.y, s);
    s = fmaf(a1.z, b1.z, s); s = fmaf(a1.w, b1.w, s);
    s = fmaf(a2.x, b2.x, s); s = fmaf(a2.y, b2.y, s);
    s = fmaf(a2.z, b2.z, s); s = fmaf(a2.w, b2.w, s);
    s = fmaf(a3.x, b3.x, s); s = fmaf(a3.y, b3.y, s);
    s = fmaf(a3.z, b3.z, s); s = fmaf(a3.w, b3.w, s);
    return s;
}

__global__ __launch_bounds__(THREADS)
void dff_kernel(const float* __restrict__ inp,
                const int* __restrict__ mask,
                const float* __restrict__ W,
                const float* __restrict__ B,
                float* __restrict__ out,
                int n_tokens)
{
    const int lane  = threadIdx.x & 31;
    const int token = blockIdx.x * 8 + (threadIdx.x >> 5);
    if (token >= n_tokens) return;

    // Stage input row in registers: lane l covers [l*4, l*4+4) at 0,128,256,384.
    const float* in_row = inp + (size_t)token * HIDDEN;
    const float4 a0 = *reinterpret_cast<const float4*>(in_row + 0   + lane * 4);
    const float4 a1 = *reinterpret_cast<const float4*>(in_row + 128 + lane * 4);
    const float4 a2 = *reinterpret_cast<const float4*>(in_row + 256 + lane * 4);
    const float4 a3 = *reinterpret_cast<const float4*>(in_row + 384 + lane * 4);

    // Lane l owns candidate l's index and bias.
    const int midx   = mask[(size_t)token * NCAND + lane];
    const float bval = __ldg(B + midx);

    float res = 0.f;

    #pragma unroll
    for (int c = 0; c < NCAND; c += 2) {
        const int idx0 = __shfl_sync(0xFFFFFFFFu, midx, c);
        const int idx1 = __shfl_sync(0xFFFFFFFFu, midx, c + 1);
        const float* w0 = W + (size_t)idx0 * HIDDEN;
        const float* w1 = W + (size_t)idx1 * HIDDEN;

        // 8 independent 128B loads in flight (skip L1 — no reuse of random rows).
        const float4 b0 = __ldcg(reinterpret_cast<const float4*>(w0 + 0   + lane * 4));
        const float4 b1 = __ldcg(reinterpret_cast<const float4*>(w0 + 128 + lane * 4));
        const float4 b2 = __ldcg(reinterpret_cast<const float4*>(w0 + 256 + lane * 4));
        const float4 b3 = __ldcg(reinterpret_cast<const float4*>(w0 + 384 + lane * 4));
        const float4 c0 = __ldcg(reinterpret_cast<const float4*>(w1 + 0   + lane * 4));
        const float4 c1 = __ldcg(reinterpret_cast<const float4*>(w1 + 128 + lane * 4));
        const float4 c2 = __ldcg(reinterpret_cast<const float4*>(w1 + 256 + lane * 4));
        const float4 c3 = __ldcg(reinterpret_cast<const float4*>(w1 + 384 + lane * 4));

        float s0 = dot16(a0, a1, a2, a3, b0, b1, b2, b3);
        float s1 = dot16(a0, a1, a2, a3, c0, c1, c2, c3);

        // Interleaved xor-reductions (all lanes end with the full sums).
        #pragma unroll
        for (int off = 16; off > 0; off >>= 1) {
            s0 += __shfl_xor_sync(0xFFFFFFFFu, s0, off);
            s1 += __shfl_xor_sync(0xFFFFFFFFu, s1, off);
        }

        if (lane == c)     res = s0;
        if (lane == c + 1) res = s1;
    }

    // Coalesced 128B store: lane l writes candidate l.
    out[(size_t)token * NCAND + lane] = fmaxf(res + bval, 0.0f);
}

extern "C" void kernel_launch(void* const* d_in, const int* in_sizes, int n_in,
                              void* d_out, int out_size)
{
    const float* inp  = (const float*)d_in[0];
    const int*   mask = (const int*)d_in[1];
    const float* W    = (const float*)d_in[2];
    const float* B    = (const float*)d_in[3];
    float* out = (float*)d_out;

    const int n_tokens = in_sizes[0] / HIDDEN;   // 8192
    const int n_blocks = (n_tokens + 7) / 8;     // 1024

    dff_kernel<<<n_blocks, THREADS>>>(inp, mask, W, B, out, n_tokens);
}

// round 4
// speedup vs baseline: 1.3189x; 1.0008x over previous
#include <cuda_runtime.h>
#include <cuda_fp16.h>
#include <cstdint>

// DynamicFeedForward:
//   input_value [4,2048,512] f32
//   mask_tensor [4,2048,32] i32
//   weight      [50000,512] f32
//   bias        [50000]     f32
// out[b,s,m] = relu( dot(input[b,s,:], weight[mask[b,s,m],:]) + bias[mask[b,s,m]] )
//
// Strategy: gather is L2-sector-bandwidth bound (2KB/ref in fp32 = 537MB).
// Repack W -> fp16 scratch each call (deterministic), halving gathered bytes.

static constexpr int HIDDEN   = 512;
static constexpr int NCAND    = 32;
static constexpr int NROWS    = 50000;
static constexpr int THREADS  = 256;   // 8 warps = 8 tokens per CTA

__device__ __align__(16) __half g_wh[(size_t)NROWS * HIDDEN];   // 51.2 MB scratch

// ---------------- conversion: fp32 W -> fp16 table ----------------
__global__ __launch_bounds__(256)
void convert_kernel(const float* __restrict__ W, int n_vec8)
{
    int i = blockIdx.x * blockDim.x + threadIdx.x;   // one thread = 8 floats
    if (i >= n_vec8) return;
    const float4* w4 = reinterpret_cast<const float4*>(W) + (size_t)i * 2;
    float4 f0 = __ldcs(w4 + 0);
    float4 f1 = __ldcs(w4 + 1);
    __half2 h[4];
    h[0] = __floats2half2_rn(f0.x, f0.y);
    h[1] = __floats2half2_rn(f0.z, f0.w);
    h[2] = __floats2half2_rn(f1.x, f1.y);
    h[3] = __floats2half2_rn(f1.z, f1.w);
    reinterpret_cast<uint4*>(g_wh)[i] = *reinterpret_cast<uint4*>(h);
}

// ---------------- gather / dot ----------------
// Lane l owns halves [8l, 8l+8) and [256+8l, 256+8l+8) of each row.
__device__ __forceinline__ float dot_row(const uint4 v0, const uint4 v1,
                                         const float4 a0, const float4 a1,
                                         const float4 a2, const float4 a3)
{
    const __half2* h0 = reinterpret_cast<const __half2*>(&v0);
    const __half2* h1 = reinterpret_cast<const __half2*>(&v1);
    float s = 0.f;
    float2 f;
    f = __half22float2(h0[0]); s = fmaf(a0.x, f.x, s); s = fmaf(a0.y, f.y, s);
    f = __half22float2(h0[1]); s = fmaf(a0.z, f.x, s); s = fmaf(a0.w, f.y, s);
    f = __half22float2(h0[2]); s = fmaf(a1.x, f.x, s); s = fmaf(a1.y, f.y, s);
    f = __half22float2(h0[3]); s = fmaf(a1.z, f.x, s); s = fmaf(a1.w, f.y, s);
    f = __half22float2(h1[0]); s = fmaf(a2.x, f.x, s); s = fmaf(a2.y, f.y, s);
    f = __half22float2(h1[1]); s = fmaf(a2.z, f.x, s); s = fmaf(a2.w, f.y, s);
    f = __half22float2(h1[2]); s = fmaf(a3.x, f.x, s); s = fmaf(a3.y, f.y, s);
    f = __half22float2(h1[3]); s = fmaf(a3.z, f.x, s); s = fmaf(a3.w, f.y, s);
    return s;
}

__global__ __launch_bounds__(THREADS)
void dff_kernel(const float* __restrict__ inp,
                const int* __restrict__ mask,
                const float* __restrict__ B,
                float* __restrict__ out,
                int n_tokens)
{
    const int lane  = threadIdx.x & 31;
    const int token = blockIdx.x * 8 + (threadIdx.x >> 5);
    if (token >= n_tokens) return;

    // Stage this lane's 16 input floats: [8l,8l+8) and [256+8l,256+8l+8).
    const float* in_row = inp + (size_t)token * HIDDEN;
    const float4 a0 = *reinterpret_cast<const float4*>(in_row + 8 * lane + 0);
    const float4 a1 = *reinterpret_cast<const float4*>(in_row + 8 * lane + 4);
    const float4 a2 = *reinterpret_cast<const float4*>(in_row + 256 + 8 * lane + 0);
    const float4 a3 = *reinterpret_cast<const float4*>(in_row + 256 + 8 * lane + 4);

    // Lane l owns candidate l's index and bias.
    const int midx   = mask[(size_t)token * NCAND + lane];
    const float bval = __ldg(B + midx);

    float res = 0.f;

    #pragma unroll
    for (int c = 0; c < NCAND; c += 4) {
        int idx[4];
        uint4 v0[4], v1[4];
        #pragma unroll
        for (int k = 0; k < 4; k++) {
            idx[k] = __shfl_sync(0xFFFFFFFFu, midx, c + k);
            const __half* w = g_wh + (size_t)idx[k] * HIDDEN;
            // two fully-dense 512B spans per row (no half-used sectors)
            v0[k] = __ldcg(reinterpret_cast<const uint4*>(w + 8 * lane));
            v1[k] = __ldcg(reinterpret_cast<const uint4*>(w + 256 + 8 * lane));
        }

        float s[4];
        #pragma unroll
        for (int k = 0; k < 4; k++)
            s[k] = dot_row(v0[k], v1[k], a0, a1, a2, a3);

        #pragma unroll
        for (int off = 16; off > 0; off >>= 1) {
            #pragma unroll
            for (int k = 0; k < 4; k++)
                s[k] += __shfl_xor_sync(0xFFFFFFFFu, s[k], off);
        }

        #pragma unroll
        for (int k = 0; k < 4; k++)
            if (lane == c + k) res = s[k];
    }

    // Coalesced 128B store: lane l writes candidate l.
    out[(size_t)token * NCAND + lane] = fmaxf(res + bval, 0.0f);
}

extern "C" void kernel_launch(void* const* d_in, const int* in_sizes, int n_in,
                              void* d_out, int out_size)
{
    const float* inp  = (const float*)d_in[0];
    const int*   mask = (const int*)d_in[1];
    const float* W    = (const float*)d_in[2];
    const float* B    = (const float*)d_in[3];
    float* out = (float*)d_out;

    const int n_tokens = in_sizes[0] / HIDDEN;           // 8192
    const int n_vec8   = NROWS * HIDDEN / 8;             // 3.2M
    const int conv_blk = (n_vec8 + 255) / 256;

    convert_kernel<<<conv_blk, 256>>>(W, n_vec8);
    dff_kernel<<<(n_tokens + 7) / 8, THREADS>>>(inp, mask, B, out, n_tokens);
}